// round 6
// baseline (speedup 1.0000x reference)
#include <cuda_runtime.h>
#include <cstdint>

#define H 128
#define MAX_E 500000
#define MAX_N 50000
#define MT 64     // nodes per block in output GEMM

// ---------------- scratch (device globals; no runtime allocation) ----------
__device__ int    g_deg[MAX_N];        // per-node in-degree
__device__ int    g_cur[MAX_N];        // scatter cursors
__device__ int    g_off[MAX_N + 1];    // CSR offsets
__device__ int2   g_eord[MAX_E];       // (src, rid) pairs grouped by dst
__device__ float4 g_n1[MAX_N * 32];    // NORMALIZED neigh, edge layer (N x 128)
__device__ float4 g_n2[MAX_N * 32];    // node layer
__device__ float4 g_n3[MAX_N * 32];    // comp layer

// ---------------- clear counters ------------------------------------------
__global__ void k_clear(int n) {
    int i = blockIdx.x * blockDim.x + threadIdx.x;
    if (i < n) { g_deg[i] = 0; g_cur[i] = 0; }
}

// ---------------- histogram of dst ----------------------------------------
__global__ void k_hist(const int* __restrict__ dst, int E) {
    int e = blockIdx.x * blockDim.x + threadIdx.x;
    if (e < E) atomicAdd(&g_deg[dst[e]], 1);
}

// ---------------- single-block prefix scan (warp-cooperative) --------------
__global__ void k_scan(int n) {
    __shared__ int swarp[32];
    __shared__ int carry;
    int tid  = threadIdx.x;
    int lane = tid & 31;
    int wid  = tid >> 5;
    if (tid == 0) { carry = 0; g_off[0] = 0; }
    for (int base = 0; base < n; base += 1024) {
        __syncthreads();
        int c = carry;
        int i = base + tid;
        int x = (i < n) ? g_deg[i] : 0;
        int v = x;
#pragma unroll
        for (int o = 1; o < 32; o <<= 1) {
            int y = __shfl_up_sync(0xffffffffu, v, o);
            if (lane >= o) v += y;
        }
        if (lane == 31) swarp[wid] = v;
        __syncthreads();
        if (wid == 0) {
            int w = swarp[lane];
#pragma unroll
            for (int o = 1; o < 32; o <<= 1) {
                int y = __shfl_up_sync(0xffffffffu, w, o);
                if (lane >= o) w += y;
            }
            swarp[lane] = w;
        }
        __syncthreads();
        int pref = (wid > 0) ? swarp[wid - 1] : 0;
        if (i < n) g_off[i + 1] = c + pref + v;
        __syncthreads();
        if (tid == 0) carry = c + swarp[31];
    }
}

// ---------------- scatter (src,rid) pairs into CSR order -------------------
__global__ void k_scatter(const int* __restrict__ src,
                          const int* __restrict__ dst,
                          const int* __restrict__ rid, int E) {
    int e = blockIdx.x * blockDim.x + threadIdx.x;
    if (e < E) {
        int d = dst[e];
        int pos = g_off[d] + atomicAdd(&g_cur[d], 1);
        g_eord[pos] = make_int2(src[e], rid[e]);
    }
}

// ---------------- per-node aggregation: warp per dst node ------------------
__global__ void k_agg(const float4* __restrict__ ent,
                      const float4* __restrict__ rel,
                      int n) {
    int d    = blockIdx.x * (blockDim.x >> 5) + (threadIdx.x >> 5);
    int lane = threadIdx.x & 31;
    if (d >= n) return;
    int beg = g_off[d], end = g_off[d + 1];
    float4 v = ent[d * 32 + lane];

    float4 A1 = make_float4(0.f, 0.f, 0.f, 0.f);
    float4 A2 = A1, A3 = A1;
    float  S1 = 0.f, S2 = 0.f, S3 = 0.f;

    int2 p = (beg < end) ? g_eord[beg] : make_int2(0, 0);
    for (int i = beg; i < end; i++) {
        int2 cur = p;
        if (i + 1 < end) p = g_eord[i + 1];     // prefetch next pair
        float4 u  = ent[cur.x * 32 + lane];
        float4 rv = rel[cur.y * 32 + lane];
        float du = u.x * v.x + u.y * v.y + u.z * v.z + u.w * v.w;
        float dr = rv.x * v.x + rv.y * v.y + rv.z * v.z + rv.w * v.w;
#pragma unroll
        for (int o = 16; o; o >>= 1) {
            du += __shfl_xor_sync(0xffffffffu, du, o);
            dr += __shfl_xor_sync(0xffffffffu, dr, o);
        }
        // logits are O(0.1): softmax shift-invariance => no max-subtract.
        float a1 = __expf(dr);     // edge layer weight
        float a2 = __expf(du);     // node layer weight
        float a3 = a1 * a2;        // comp layer: exp(du+dr)
        S1 += a1; S2 += a2; S3 += a3;
        A1.x += a1 * rv.x; A1.y += a1 * rv.y; A1.z += a1 * rv.z; A1.w += a1 * rv.w;
        A2.x += a2 * u.x;  A2.y += a2 * u.y;  A2.z += a2 * u.z;  A2.w += a2 * u.w;
        A3.x += a3 * (u.x + rv.x); A3.y += a3 * (u.y + rv.y);
        A3.z += a3 * (u.z + rv.z); A3.w += a3 * (u.w + rv.w);
    }
    float i1 = (S1 > 0.f) ? 1.0f / S1 : 0.f;
    float i2 = (S2 > 0.f) ? 1.0f / S2 : 0.f;
    float i3 = (S3 > 0.f) ? 1.0f / S3 : 0.f;
    int o = d * 32 + lane;
    g_n1[o] = make_float4(A1.x * i1, A1.y * i1, A1.z * i1, A1.w * i1);
    g_n2[o] = make_float4(A2.x * i2, A2.y * i2, A2.z * i2, A2.w * i2);
    g_n3[o] = make_float4(A3.x * i3, A3.y * i3, A3.z * i3, A3.w * i3);
}

// ---------------- pass 3: tf32 tensor-core GEMM + tanh epilogue ------------
__device__ __forceinline__ uint32_t f2tf32(float x) {
    uint32_t r;
    asm("cvt.rna.tf32.f32 %0, %1;" : "=r"(r) : "f"(x));
    return r;
}

__device__ __forceinline__ void mma_tf32(float* c,
                                         uint32_t a0, uint32_t a1,
                                         uint32_t a2, uint32_t a3,
                                         uint32_t b0, uint32_t b1) {
    asm volatile("mma.sync.aligned.m16n8k8.row.col.f32.tf32.tf32.f32 "
                 "{%0,%1,%2,%3}, {%4,%5,%6,%7}, {%8,%9}, {%0,%1,%2,%3};"
                 : "+f"(c[0]), "+f"(c[1]), "+f"(c[2]), "+f"(c[3])
                 : "r"(a0), "r"(a1), "r"(a2), "r"(a3), "r"(b0), "r"(b1));
}

// out = ent + sum_l tanh(neigh_l @ W_l). Block: 128 threads (4 warps),
// 64 nodes per block; each warp owns 16 rows x 128 cols of C.
__global__ void __launch_bounds__(128) k_out(
        const float* __restrict__ ent,
        const float* __restrict__ We,
        const float* __restrict__ Wn,
        const float* __restrict__ Wc,
        float* __restrict__ out, int n) {
    __shared__ float sA[MT][H + 4];      // tf32-bits A tile, padded

    int tid  = threadIdx.x;
    int warp = tid >> 5;
    int lane = tid & 31;
    int g    = lane >> 2;                // group id 0..7
    int tig  = lane & 3;                 // thread-in-group 0..3
    int base = blockIdx.x * MT;

    int r0 = base + warp * 16 + g;       // fragment rows
    int r1 = r0 + 8;

    // outAcc[nt][0..3] in C-fragment layout, init from ent
    float outAcc[16][4];
#pragma unroll
    for (int nt = 0; nt < 16; nt++) {
        int col = nt * 8 + 2 * tig;
        float2 e0 = (r0 < n) ? *(const float2*)&ent[r0 * H + col]
                             : make_float2(0.f, 0.f);
        float2 e1 = (r1 < n) ? *(const float2*)&ent[r1 * H + col]
                             : make_float2(0.f, 0.f);
        outAcc[nt][0] = e0.x; outAcc[nt][1] = e0.y;
        outAcc[nt][2] = e1.x; outAcc[nt][3] = e1.y;
    }

    const float*  Ws[3] = {We, Wn, Wc};
    const float4* Ns[3] = {g_n1, g_n2, g_n3};

    for (int L = 0; L < 3; L++) {
        __syncthreads();
        // stage A tile (64 x 128), converting to tf32 bits
        const float4* Nm = Ns[L];
        for (int i = tid; i < MT * 32; i += 128) {
            int rr = i >> 5, cc = i & 31;
            float4 val = (base + rr < n) ? Nm[(base + rr) * 32 + cc]
                                         : make_float4(0.f, 0.f, 0.f, 0.f);
            float4 t;
            t.x = __uint_as_float(f2tf32(val.x));
            t.y = __uint_as_float(f2tf32(val.y));
            t.z = __uint_as_float(f2tf32(val.z));
            t.w = __uint_as_float(f2tf32(val.w));
            *(float4*)&sA[rr][cc * 4] = t;
        }
        __syncthreads();

        float C[16][4];
#pragma unroll
        for (int nt = 0; nt < 16; nt++)
#pragma unroll
            for (int q = 0; q < 4; q++) C[nt][q] = 0.f;

        const float* W = Ws[L];
        int ra = warp * 16 + g;
#pragma unroll 4
        for (int kk = 0; kk < 16; kk++) {
            int c0 = kk * 8 + tig;
            uint32_t a0 = __float_as_uint(sA[ra][c0]);
            uint32_t a1 = __float_as_uint(sA[ra + 8][c0]);
            uint32_t a2 = __float_as_uint(sA[ra][c0 + 4]);
            uint32_t a3 = __float_as_uint(sA[ra + 8][c0 + 4]);
            const float* Wk = W + c0 * H;       // row k = c0, row k+4 at +4H
#pragma unroll
            for (int nt = 0; nt < 16; nt++) {
                uint32_t b0 = f2tf32(__ldg(&Wk[nt * 8 + g]));
                uint32_t b1 = f2tf32(__ldg(&Wk[4 * H + nt * 8 + g]));
                mma_tf32(C[nt], a0, a1, a2, a3, b0, b1);
            }
        }
#pragma unroll
        for (int nt = 0; nt < 16; nt++)
#pragma unroll
            for (int q = 0; q < 4; q++) outAcc[nt][q] += tanhf(C[nt][q]);
    }

    // store in fragment layout (float2 pairs)
#pragma unroll
    for (int nt = 0; nt < 16; nt++) {
        int col = nt * 8 + 2 * tig;
        if (r0 < n) *(float2*)&out[r0 * H + col] = make_float2(outAcc[nt][0], outAcc[nt][1]);
        if (r1 < n) *(float2*)&out[r1 * H + col] = make_float2(outAcc[nt][2], outAcc[nt][3]);
    }
}

// ---------------- launch ---------------------------------------------------
extern "C" void kernel_launch(void* const* d_in, const int* in_sizes, int n_in,
                              void* d_out, int out_size) {
    const float* ent = (const float*)d_in[0];
    const float* rel = (const float*)d_in[1];
    const float* We  = (const float*)d_in[2];
    const float* Wn  = (const float*)d_in[3];
    const float* Wc  = (const float*)d_in[4];
    const int*   src = (const int*)d_in[5];
    const int*   dst = (const int*)d_in[6];
    const int*   rid = (const int*)d_in[7];
    float*       out = (float*)d_out;

    int n = in_sizes[0] / H;      // 50000
    int E = in_sizes[5];          // 500000
    if (n > MAX_N) n = MAX_N;
    if (E > MAX_E) E = MAX_E;

    k_clear<<<(n + 255) / 256, 256>>>(n);
    k_hist<<<(E + 255) / 256, 256>>>(dst, E);
    k_scan<<<1, 1024>>>(n);
    k_scatter<<<(E + 255) / 256, 256>>>(src, dst, rid, E);

    // warp per node: 8 nodes per 256-thread block
    k_agg<<<(n + 7) / 8, 256>>>((const float4*)ent, (const float4*)rel, n);

    k_out<<<(n + MT - 1) / MT, 128>>>(ent, We, Wn, Wc, out, n);
}

// round 10
// speedup vs baseline: 1.2831x; 1.2831x over previous
#include <cuda_runtime.h>
#include <cstdint>

#define H 128
#define MAX_E 500000
#define MAX_N 50000
#define MT 128            // nodes per block in output GEMM
#define SAPITCH 132       // padded row pitch (floats) for smem tiles

// ---------------- scratch (device globals; no runtime allocation) ----------
__device__ int    g_deg[MAX_N];        // per-node in-degree
__device__ int    g_cur[MAX_N];        // scatter cursors
__device__ int    g_off[MAX_N + 1];    // CSR offsets
__device__ int2   g_eord[MAX_E];       // (src, rid) pairs grouped by dst
__device__ float4 g_n1[MAX_N * 32];    // NORMALIZED neigh (tf32-rounded)
__device__ float4 g_n2[MAX_N * 32];
__device__ float4 g_n3[MAX_N * 32];

// ---------------- clear counters ------------------------------------------
__global__ void k_clear(int n) {
    int i = blockIdx.x * blockDim.x + threadIdx.x;
    if (i < n) { g_deg[i] = 0; g_cur[i] = 0; }
}

// ---------------- histogram of dst ----------------------------------------
__global__ void k_hist(const int* __restrict__ dst, int E) {
    int e = blockIdx.x * blockDim.x + threadIdx.x;
    if (e < E) atomicAdd(&g_deg[dst[e]], 1);
}

// ---------------- single-block prefix scan (warp-cooperative) --------------
__global__ void k_scan(int n) {
    __shared__ int swarp[32];
    __shared__ int carry;
    int tid  = threadIdx.x;
    int lane = tid & 31;
    int wid  = tid >> 5;
    if (tid == 0) { carry = 0; g_off[0] = 0; }
    for (int base = 0; base < n; base += 1024) {
        __syncthreads();
        int c = carry;
        int i = base + tid;
        int x = (i < n) ? g_deg[i] : 0;
        int v = x;
#pragma unroll
        for (int o = 1; o < 32; o <<= 1) {
            int y = __shfl_up_sync(0xffffffffu, v, o);
            if (lane >= o) v += y;
        }
        if (lane == 31) swarp[wid] = v;
        __syncthreads();
        if (wid == 0) {
            int w = swarp[lane];
#pragma unroll
            for (int o = 1; o < 32; o <<= 1) {
                int y = __shfl_up_sync(0xffffffffu, w, o);
                if (lane >= o) w += y;
            }
            swarp[lane] = w;
        }
        __syncthreads();
        int pref = (wid > 0) ? swarp[wid - 1] : 0;
        if (i < n) g_off[i + 1] = c + pref + v;
        __syncthreads();
        if (tid == 0) carry = c + swarp[31];
    }
}

// ---------------- scatter (src,rid) pairs into CSR order -------------------
__global__ void k_scatter(const int* __restrict__ src,
                          const int* __restrict__ dst,
                          const int* __restrict__ rid, int E) {
    int e = blockIdx.x * blockDim.x + threadIdx.x;
    if (e < E) {
        int d = dst[e];
        int pos = g_off[d] + atomicAdd(&g_cur[d], 1);
        g_eord[pos] = make_int2(src[e], rid[e]);
    }
}

// ---------------- tf32 helpers --------------------------------------------
__device__ __forceinline__ uint32_t f2tf32(float x) {
    uint32_t r;
    asm("cvt.rna.tf32.f32 %0, %1;" : "=r"(r) : "f"(x));
    return r;
}
__device__ __forceinline__ float tf32f(float x) {
    return __uint_as_float(f2tf32(x));
}

// ---------------- per-node aggregation: warp per dst node ------------------
__global__ void k_agg(const float4* __restrict__ ent,
                      const float4* __restrict__ rel,
                      int n) {
    int d    = blockIdx.x * (blockDim.x >> 5) + (threadIdx.x >> 5);
    int lane = threadIdx.x & 31;
    if (d >= n) return;
    int beg = g_off[d], end = g_off[d + 1];
    float4 v = ent[d * 32 + lane];

    float4 A1 = make_float4(0.f, 0.f, 0.f, 0.f);
    float4 A2 = A1, A3 = A1;
    float  S1 = 0.f, S2 = 0.f, S3 = 0.f;

    int2 p = (beg < end) ? g_eord[beg] : make_int2(0, 0);
    for (int i = beg; i < end; i++) {
        int2 cur = p;
        if (i + 1 < end) p = g_eord[i + 1];     // prefetch next pair
        float4 u  = ent[cur.x * 32 + lane];
        float4 rv = rel[cur.y * 32 + lane];
        float du = u.x * v.x + u.y * v.y + u.z * v.z + u.w * v.w;
        float dr = rv.x * v.x + rv.y * v.y + rv.z * v.z + rv.w * v.w;
#pragma unroll
        for (int o = 16; o; o >>= 1) {
            du += __shfl_xor_sync(0xffffffffu, du, o);
            dr += __shfl_xor_sync(0xffffffffu, dr, o);
        }
        // logits are O(0.1): softmax shift-invariance => no max-subtract.
        float a1 = __expf(dr);     // edge layer weight
        float a2 = __expf(du);     // node layer weight
        float a3 = a1 * a2;        // comp layer: exp(du+dr)
        S1 += a1; S2 += a2; S3 += a3;
        A1.x += a1 * rv.x; A1.y += a1 * rv.y; A1.z += a1 * rv.z; A1.w += a1 * rv.w;
        A2.x += a2 * u.x;  A2.y += a2 * u.y;  A2.z += a2 * u.z;  A2.w += a2 * u.w;
        A3.x += a3 * (u.x + rv.x); A3.y += a3 * (u.y + rv.y);
        A3.z += a3 * (u.z + rv.z); A3.w += a3 * (u.w + rv.w);
    }
    float i1 = (S1 > 0.f) ? 1.0f / S1 : 0.f;
    float i2 = (S2 > 0.f) ? 1.0f / S2 : 0.f;
    float i3 = (S3 > 0.f) ? 1.0f / S3 : 0.f;
    int o = d * 32 + lane;
    // store tf32-rounded so k_out can feed mma directly
    g_n1[o] = make_float4(tf32f(A1.x * i1), tf32f(A1.y * i1),
                          tf32f(A1.z * i1), tf32f(A1.w * i1));
    g_n2[o] = make_float4(tf32f(A2.x * i2), tf32f(A2.y * i2),
                          tf32f(A2.z * i2), tf32f(A2.w * i2));
    g_n3[o] = make_float4(tf32f(A3.x * i3), tf32f(A3.y * i3),
                          tf32f(A3.z * i3), tf32f(A3.w * i3));
}

// ---------------- pass 3: tf32 tensor-core GEMM + tanh epilogue ------------
__device__ __forceinline__ void mma_tf32(float* c,
                                         uint32_t a0, uint32_t a1,
                                         uint32_t a2, uint32_t a3,
                                         uint32_t b0, uint32_t b1) {
    asm volatile("mma.sync.aligned.m16n8k8.row.col.f32.tf32.tf32.f32 "
                 "{%0,%1,%2,%3}, {%4,%5,%6,%7}, {%8,%9}, {%0,%1,%2,%3};"
                 : "+f"(c[0]), "+f"(c[1]), "+f"(c[2]), "+f"(c[3])
                 : "r"(a0), "r"(a1), "r"(a2), "r"(a3), "r"(b0), "r"(b1));
}

// out = ent + sum_l tanh(neigh_l @ W_l).
// Block: 256 threads (8 warps, 2/SMSP), 128 nodes/block.
// smem: sA 128x132 (tf32 A tile), sW 128x132 (tf32 W, transposed n-major).
__global__ void __launch_bounds__(256) k_out(
        const float* __restrict__ ent,
        const float* __restrict__ We,
        const float* __restrict__ Wn,
        const float* __restrict__ Wc,
        float* __restrict__ out, int n) {
    extern __shared__ float sm[];
    float* sA = sm;                       // [MT][SAPITCH]
    float* sW = sm + MT * SAPITCH;        // [H][SAPITCH] transposed: sW[n][k]

    int tid  = threadIdx.x;
    int warp = tid >> 5;
    int lane = tid & 31;
    int g    = lane >> 2;                 // 0..7
    int tig  = lane & 3;                  // 0..3
    int base = blockIdx.x * MT;
    int wm   = warp * 16;
    int r0   = base + wm + g;             // fragment rows
    int r1   = r0 + 8;

    const float*  Ws[3] = {We, Wn, Wc};
    const float4* Ns[3] = {g_n1, g_n2, g_n3};

#pragma unroll 1
    for (int L = 0; L < 3; L++) {
        if (L) __syncthreads();           // prior layer's smem reads done
        // stage A tile (already tf32-rounded by k_agg)
        const float4* Nm = Ns[L];
        for (int idx = tid; idx < MT * 32; idx += 256) {
            int rr = idx >> 5, cc = idx & 31;
            float4 val = (base + rr < n) ? Nm[(base + rr) * 32 + cc]
                                         : make_float4(0.f, 0.f, 0.f, 0.f);
            *(float4*)&sA[rr * SAPITCH + cc * 4] = val;
        }
        // stage W transposed + tf32 convert (coalesced LDG, 4-way-conflict STS)
        const float* W = Ws[L];
        for (int idx = tid; idx < H * H; idx += 256) {
            int k = idx >> 7, nn = idx & 127;
            sW[nn * SAPITCH + k] = tf32f(W[idx]);
        }
        __syncthreads();

        float C[16][4];
#pragma unroll
        for (int nt = 0; nt < 16; nt++)
#pragma unroll
            for (int q = 0; q < 4; q++) C[nt][q] = 0.f;

        // preload A frags for kk=0
        const float* Ar0 = &sA[(wm + g) * SAPITCH];
        const float* Ar1 = &sA[(wm + g + 8) * SAPITCH];
        uint32_t a0 = __float_as_uint(Ar0[tig]);
        uint32_t a1 = __float_as_uint(Ar1[tig]);
        uint32_t a2 = __float_as_uint(Ar0[tig + 4]);
        uint32_t a3 = __float_as_uint(Ar1[tig + 4]);

#pragma unroll 1
        for (int kk = 0; kk < 16; kk++) {
            uint32_t na0 = a0, na1 = a1, na2 = a2, na3 = a3;
            if (kk < 15) {                // prefetch next kk's A frags
                int c0n = (kk + 1) * 8 + tig;
                na0 = __float_as_uint(Ar0[c0n]);
                na1 = __float_as_uint(Ar1[c0n]);
                na2 = __float_as_uint(Ar0[c0n + 4]);
                na3 = __float_as_uint(Ar1[c0n + 4]);
            }
            int kb = kk * 8 + tig;
#pragma unroll
            for (int nt = 0; nt < 16; nt++) {
                const float* Wn_ = &sW[(nt * 8 + g) * SAPITCH + kb];
                uint32_t b0 = __float_as_uint(Wn_[0]);   // conflict-free LDS
                uint32_t b1 = __float_as_uint(Wn_[4]);
                mma_tf32(C[nt], a0, a1, a2, a3, b0, b1);
            }
            a0 = na0; a1 = na1; a2 = na2; a3 = na3;
        }

        // epilogue: out = (L==0 ? ent : out) + tanh(C), fragment layout
#pragma unroll
        for (int nt = 0; nt < 16; nt++) {
            int col = nt * 8 + 2 * tig;
            if (r0 < n) {
                float2 o0 = (L == 0) ? *(const float2*)&ent[r0 * H + col]
                                     : *(const float2*)&out[r0 * H + col];
                o0.x += tanhf(C[nt][0]);
                o0.y += tanhf(C[nt][1]);
                *(float2*)&out[r0 * H + col] = o0;
            }
            if (r1 < n) {
                float2 o1 = (L == 0) ? *(const float2*)&ent[r1 * H + col]
                                     : *(const float2*)&out[r1 * H + col];
                o1.x += tanhf(C[nt][2]);
                o1.y += tanhf(C[nt][3]);
                *(float2*)&out[r1 * H + col] = o1;
            }
        }
    }
}

// ---------------- launch ---------------------------------------------------
extern "C" void kernel_launch(void* const* d_in, const int* in_sizes, int n_in,
                              void* d_out, int out_size) {
    const float* ent = (const float*)d_in[0];
    const float* rel = (const float*)d_in[1];
    const float* We  = (const float*)d_in[2];
    const float* Wn  = (const float*)d_in[3];
    const float* Wc  = (const float*)d_in[4];
    const int*   src = (const int*)d_in[5];
    const int*   dst = (const int*)d_in[6];
    const int*   rid = (const int*)d_in[7];
    float*       out = (float*)d_out;

    int n = in_sizes[0] / H;      // 50000
    int E = in_sizes[5];          // 500000
    if (n > MAX_N) n = MAX_N;
    if (E > MAX_E) E = MAX_E;

    k_clear<<<(n + 255) / 256, 256>>>(n);
    k_hist<<<(E + 255) / 256, 256>>>(dst, E);
    k_scan<<<1, 1024>>>(n);
    k_scatter<<<(E + 255) / 256, 256>>>(src, dst, rid, E);

    // warp per node: 8 nodes per 256-thread block
    k_agg<<<(n + 7) / 8, 256>>>((const float4*)ent, (const float4*)rel, n);

    int smem = (MT + H) * SAPITCH * sizeof(float);   // 135168 bytes
    cudaFuncSetAttribute(k_out, cudaFuncAttributeMaxDynamicSharedMemorySize, smem);
    k_out<<<(n + MT - 1) / MT, 256, smem>>>(ent, We, Wn, Wc, out, n);
}

// round 11
// speedup vs baseline: 2.1643x; 1.6867x over previous
#include <cuda_runtime.h>
#include <cstdint>

#define H 128
#define MAX_E 500000
#define MAX_N 50000
#define MT 128            // nodes per block in output GEMM
#define PA 132            // sA pitch (floats)
#define PW 192            // sW pitch (floats), 16 blocks of 12

// ---------------- scratch (device globals; no runtime allocation) ----------
__device__ int    g_deg[MAX_N];
__device__ int    g_cur[MAX_N];
__device__ int    g_off[MAX_N + 1];
__device__ int2   g_eord[MAX_E];       // (src, rid) pairs grouped by dst
__device__ float4 g_n1[MAX_N * 32];    // NORMALIZED neigh (fp32)
__device__ float4 g_n2[MAX_N * 32];
__device__ float4 g_n3[MAX_N * 32];

// ---------------- clear counters ------------------------------------------
__global__ void k_clear(int n) {
    int i = blockIdx.x * blockDim.x + threadIdx.x;
    if (i < n) { g_deg[i] = 0; g_cur[i] = 0; }
}

// ---------------- histogram of dst ----------------------------------------
__global__ void k_hist(const int* __restrict__ dst, int E) {
    int e = blockIdx.x * blockDim.x + threadIdx.x;
    if (e < E) atomicAdd(&g_deg[dst[e]], 1);
}

// ---------------- single-block prefix scan (warp-cooperative) --------------
__global__ void k_scan(int n) {
    __shared__ int swarp[32];
    __shared__ int carry;
    int tid  = threadIdx.x;
    int lane = tid & 31;
    int wid  = tid >> 5;
    if (tid == 0) { carry = 0; g_off[0] = 0; }
    for (int base = 0; base < n; base += 1024) {
        __syncthreads();
        int c = carry;
        int i = base + tid;
        int x = (i < n) ? g_deg[i] : 0;
        int v = x;
#pragma unroll
        for (int o = 1; o < 32; o <<= 1) {
            int y = __shfl_up_sync(0xffffffffu, v, o);
            if (lane >= o) v += y;
        }
        if (lane == 31) swarp[wid] = v;
        __syncthreads();
        if (wid == 0) {
            int w = swarp[lane];
#pragma unroll
            for (int o = 1; o < 32; o <<= 1) {
                int y = __shfl_up_sync(0xffffffffu, w, o);
                if (lane >= o) w += y;
            }
            swarp[lane] = w;
        }
        __syncthreads();
        int pref = (wid > 0) ? swarp[wid - 1] : 0;
        if (i < n) g_off[i + 1] = c + pref + v;
        __syncthreads();
        if (tid == 0) carry = c + swarp[31];
    }
}

// ---------------- scatter (src,rid) pairs into CSR order -------------------
__global__ void k_scatter(const int* __restrict__ src,
                          const int* __restrict__ dst,
                          const int* __restrict__ rid, int E) {
    int e = blockIdx.x * blockDim.x + threadIdx.x;
    if (e < E) {
        int d = dst[e];
        int pos = g_off[d] + atomicAdd(&g_cur[d], 1);
        g_eord[pos] = make_int2(src[e], rid[e]);
    }
}

// ---------------- per-node aggregation: half-warp per edge -----------------
// 16 lanes per edge, 2 edges in flight per warp. Lane q covers dims
// [8q, 8q+8) as two float4 chunks (2q, 2q+1).
__device__ __forceinline__ float dot4(float4 a, float4 b) {
    return a.x * b.x + a.y * b.y + a.z * b.z + a.w * b.w;
}

__global__ void k_agg(const float4* __restrict__ ent,
                      const float4* __restrict__ rel,
                      int n) {
    int d    = blockIdx.x * (blockDim.x >> 5) + (threadIdx.x >> 5);
    int lane = threadIdx.x & 31;
    if (d >= n) return;                       // warp-uniform
    int half = lane >> 4, q = lane & 15;
    int beg = g_off[d], end = g_off[d + 1];

    float4 va = ent[d * 32 + 2 * q];
    float4 vb = ent[d * 32 + 2 * q + 1];

    float4 Z = make_float4(0.f, 0.f, 0.f, 0.f);
    float4 A1a = Z, A1b = Z, A2a = Z, A2b = Z, A3a = Z, A3b = Z;
    float  S1 = 0.f, S2 = 0.f, S3 = 0.f;

    int iters = (end - beg + 1) >> 1;
    for (int it = 0; it < iters; it++) {
        int  i   = beg + 2 * it + half;
        bool val = i < end;
        int2 e   = g_eord[val ? i : beg];
        const float4* us = ent + e.x * 32;
        const float4* rs = rel + e.y * 32;
        float4 ua = us[2 * q], ub = us[2 * q + 1];
        float4 ra = rs[2 * q], rb = rs[2 * q + 1];
        float du = dot4(ua, va) + dot4(ub, vb);
        float dr = dot4(ra, va) + dot4(rb, vb);
#pragma unroll
        for (int o = 8; o; o >>= 1) {         // reduce within 16-lane group
            du += __shfl_xor_sync(0xffffffffu, du, o);
            dr += __shfl_xor_sync(0xffffffffu, dr, o);
        }
        // logits are O(0.1): softmax shift-invariance => no max-subtract.
        float a1 = val ? __expf(dr) : 0.f;    // edge layer weight
        float a2 = val ? __expf(du) : 0.f;    // node layer weight
        float a3 = a1 * a2;                   // comp layer: exp(du+dr)
        S1 += a1; S2 += a2; S3 += a3;
        A1a.x += a1 * ra.x; A1a.y += a1 * ra.y; A1a.z += a1 * ra.z; A1a.w += a1 * ra.w;
        A1b.x += a1 * rb.x; A1b.y += a1 * rb.y; A1b.z += a1 * rb.z; A1b.w += a1 * rb.w;
        A2a.x += a2 * ua.x; A2a.y += a2 * ua.y; A2a.z += a2 * ua.z; A2a.w += a2 * ua.w;
        A2b.x += a2 * ub.x; A2b.y += a2 * ub.y; A2b.z += a2 * ub.z; A2b.w += a2 * ub.w;
        A3a.x += a3 * (ua.x + ra.x); A3a.y += a3 * (ua.y + ra.y);
        A3a.z += a3 * (ua.z + ra.z); A3a.w += a3 * (ua.w + ra.w);
        A3b.x += a3 * (ub.x + rb.x); A3b.y += a3 * (ub.y + rb.y);
        A3b.z += a3 * (ub.z + rb.z); A3b.w += a3 * (ub.w + rb.w);
    }

#define R16(x) x += __shfl_xor_sync(0xffffffffu, x, 16)
    R16(S1); R16(S2); R16(S3);
    R16(A1a.x); R16(A1a.y); R16(A1a.z); R16(A1a.w);
    R16(A1b.x); R16(A1b.y); R16(A1b.z); R16(A1b.w);
    R16(A2a.x); R16(A2a.y); R16(A2a.z); R16(A2a.w);
    R16(A2b.x); R16(A2b.y); R16(A2b.z); R16(A2b.w);
    R16(A3a.x); R16(A3a.y); R16(A3a.z); R16(A3a.w);
    R16(A3b.x); R16(A3b.y); R16(A3b.z); R16(A3b.w);
#undef R16

    float i1 = (S1 > 0.f) ? 1.0f / S1 : 0.f;
    float i2 = (S2 > 0.f) ? 1.0f / S2 : 0.f;
    float i3 = (S3 > 0.f) ? 1.0f / S3 : 0.f;
    int o = d * 32 + 2 * q;
    if (half == 0) {
        g_n1[o]     = make_float4(A1a.x * i1, A1a.y * i1, A1a.z * i1, A1a.w * i1);
        g_n1[o + 1] = make_float4(A1b.x * i1, A1b.y * i1, A1b.z * i1, A1b.w * i1);
        g_n2[o]     = make_float4(A2a.x * i2, A2a.y * i2, A2a.z * i2, A2a.w * i2);
        g_n2[o + 1] = make_float4(A2b.x * i2, A2b.y * i2, A2b.z * i2, A2b.w * i2);
    } else {
        g_n3[o]     = make_float4(A3a.x * i3, A3a.y * i3, A3a.z * i3, A3a.w * i3);
        g_n3[o + 1] = make_float4(A3b.x * i3, A3b.y * i3, A3b.z * i3, A3b.w * i3);
    }
}

// ---------------- pass 3: packed-f32x2 GEMM + tanh epilogue ----------------
__device__ __forceinline__ void fma2(unsigned long long& c,
                                     unsigned long long a,
                                     unsigned long long b) {
    asm("fma.rn.f32x2 %0, %1, %2, %0;" : "+l"(c) : "l"(a), "l"(b));
}
__device__ __forceinline__ unsigned long long pack2(float x, float y) {
    unsigned long long r;
    asm("mov.b64 %0, {%1, %2};" : "=l"(r) : "f"(x), "f"(y));
    return r;
}
__device__ __forceinline__ void unpack2(unsigned long long v, float& x, float& y) {
    asm("mov.b64 {%0, %1}, %2;" : "=f"(x), "=f"(y) : "l"(v));
}

// W smem de-swizzle: col -> 12*(col/8) + (col%8); spreads the 16 col-blocks
// over banks so the per-thread 32B b-reads are 2-way instead of 4-way.
__device__ __forceinline__ int swc_f4(int cc) {   // cc = col/4 (float4 index)
    return 12 * (cc >> 1) + 4 * (cc & 1);
}

// out = ent + sum_l tanh(neigh_l @ W_l). Block: 256 threads, 128 nodes/block.
// Thread (tx,ty) computes rows 8ty..8ty+7, cols 8tx..8tx+7; C packed (cols).
__global__ void __launch_bounds__(256) k_out(
        const float* __restrict__ ent,
        const float* __restrict__ We,
        const float* __restrict__ Wn,
        const float* __restrict__ Wc,
        float* __restrict__ out, int n) {
    extern __shared__ float sm[];
    float* sA = sm;                 // [128][PA]  node tile, natural layout
    float* sW = sm + MT * PA;       // [128][PW]  W tile, block-swizzled cols

    int tid = threadIdx.x;
    int tx  = tid & 15;
    int ty  = tid >> 4;
    int base = blockIdx.x * MT;

    // outAcc[i][j]: row base+8ty+i, col 8tx+j; init from ent
    float outAcc[8][8];
#pragma unroll
    for (int i = 0; i < 8; i++) {
        int r = base + 8 * ty + i;
        if (r < n) {
            float4 e0 = *(const float4*)&ent[r * H + 8 * tx];
            float4 e1 = *(const float4*)&ent[r * H + 8 * tx + 4];
            outAcc[i][0] = e0.x; outAcc[i][1] = e0.y; outAcc[i][2] = e0.z; outAcc[i][3] = e0.w;
            outAcc[i][4] = e1.x; outAcc[i][5] = e1.y; outAcc[i][6] = e1.z; outAcc[i][7] = e1.w;
        } else {
#pragma unroll
            for (int j = 0; j < 8; j++) outAcc[i][j] = 0.f;
        }
    }

    const float*  Ws[3] = {We, Wn, Wc};
    const float4* Ns[3] = {g_n1, g_n2, g_n3};

#pragma unroll 1
    for (int L = 0; L < 3; L++) {
        if (L) __syncthreads();
        // stage A (128 x 128 floats), natural row-major, pitch PA
        const float4* Nm = Ns[L];
        for (int idx = tid; idx < MT * 32; idx += 256) {
            int rr = idx >> 5, cc = idx & 31;
            float4 v = (base + rr < n) ? Nm[(base + rr) * 32 + cc]
                                       : make_float4(0.f, 0.f, 0.f, 0.f);
            *(float4*)&sA[rr * PA + cc * 4] = v;
        }
        // stage W with block-swizzled columns, pitch PW
        const float4* Wv = (const float4*)Ws[L];
        for (int idx = tid; idx < H * 32; idx += 256) {
            int k = idx >> 5, cc = idx & 31;
            *(float4*)&sW[k * PW + swc_f4(cc)] = Wv[k * 32 + cc];
        }
        __syncthreads();

        unsigned long long c2[8][4];
#pragma unroll
        for (int i = 0; i < 8; i++)
#pragma unroll
            for (int j = 0; j < 4; j++) c2[i][j] = 0ull;

        const float* sWt = &sW[12 * tx];         // this thread's col block
        const float* sAt = &sA[8 * ty * PA];
#pragma unroll 4
        for (int k2 = 0; k2 < 64; k2++) {
            int k = 2 * k2;
            ulonglong2 Ba0 = *(const ulonglong2*)&sWt[k * PW];
            ulonglong2 Ba1 = *(const ulonglong2*)&sWt[k * PW + 4];
            ulonglong2 Bb0 = *(const ulonglong2*)&sWt[(k + 1) * PW];
            ulonglong2 Bb1 = *(const ulonglong2*)&sWt[(k + 1) * PW + 4];
#pragma unroll
            for (int i = 0; i < 8; i++) {
                float2 av = *(const float2*)&sAt[i * PA + k];   // (a_k, a_k+1)
                unsigned long long a0 = pack2(av.x, av.x);
                unsigned long long a1 = pack2(av.y, av.y);
                fma2(c2[i][0], a0, Ba0.x); fma2(c2[i][1], a0, Ba0.y);
                fma2(c2[i][2], a0, Ba1.x); fma2(c2[i][3], a0, Ba1.y);
                fma2(c2[i][0], a1, Bb0.x); fma2(c2[i][1], a1, Bb0.y);
                fma2(c2[i][2], a1, Bb1.x); fma2(c2[i][3], a1, Bb1.y);
            }
        }

        // epilogue: outAcc += tanh(C)
#pragma unroll
        for (int i = 0; i < 8; i++)
#pragma unroll
            for (int j = 0; j < 4; j++) {
                float lo, hi;
                unpack2(c2[i][j], lo, hi);
                outAcc[i][2 * j]     += tanhf(lo);
                outAcc[i][2 * j + 1] += tanhf(hi);
            }
    }

    // store
#pragma unroll
    for (int i = 0; i < 8; i++) {
        int r = base + 8 * ty + i;
        if (r < n) {
            *(float4*)&out[r * H + 8 * tx] =
                make_float4(outAcc[i][0], outAcc[i][1], outAcc[i][2], outAcc[i][3]);
            *(float4*)&out[r * H + 8 * tx + 4] =
                make_float4(outAcc[i][4], outAcc[i][5], outAcc[i][6], outAcc[i][7]);
        }
    }
}

// ---------------- launch ---------------------------------------------------
extern "C" void kernel_launch(void* const* d_in, const int* in_sizes, int n_in,
                              void* d_out, int out_size) {
    const float* ent = (const float*)d_in[0];
    const float* rel = (const float*)d_in[1];
    const float* We  = (const float*)d_in[2];
    const float* Wn  = (const float*)d_in[3];
    const float* Wc  = (const float*)d_in[4];
    const int*   src = (const int*)d_in[5];
    const int*   dst = (const int*)d_in[6];
    const int*   rid = (const int*)d_in[7];
    float*       out = (float*)d_out;

    int n = in_sizes[0] / H;      // 50000
    int E = in_sizes[5];          // 500000
    if (n > MAX_N) n = MAX_N;
    if (E > MAX_E) E = MAX_E;

    k_clear<<<(n + 255) / 256, 256>>>(n);
    k_hist<<<(E + 255) / 256, 256>>>(dst, E);
    k_scan<<<1, 1024>>>(n);
    k_scatter<<<(E + 255) / 256, 256>>>(src, dst, rid, E);

    // warp per node: 8 nodes per 256-thread block
    k_agg<<<(n + 7) / 8, 256>>>((const float4*)ent, (const float4*)rel, n);

    int smem = (MT * PA + H * PW) * sizeof(float);   // 165,888 bytes
    cudaFuncSetAttribute(k_out, cudaFuncAttributeMaxDynamicSharedMemorySize, smem);
    k_out<<<(n + MT - 1) / MT, 256, smem>>>(ent, We, Wn, Wc, out, n);
}